// round 12
// baseline (speedup 1.0000x reference)
#include <cuda_runtime.h>
#include <math.h>

#define E_CNT 262144
#define N_CNT 16384

// XOR swizzle within a 128-float4 (512-float) row: kills 4-way LDS conflicts
#define SW4(f) ((f) ^ (((f) >> 3) & 7))

// ---------------- f32x2 packed-FMA helpers (bit-exact fp32) ----------------
__device__ __forceinline__ unsigned long long pk2(float lo, float hi) {
    unsigned long long r;
    asm("mov.b64 %0, {%1, %2};" : "=l"(r) : "f"(lo), "f"(hi));
    return r;
}
__device__ __forceinline__ void fma2(unsigned long long& d,
                                     unsigned long long a, unsigned long long b) {
    asm("fma.rn.f32x2 %0, %1, %2, %0;" : "+l"(d) : "l"(a), "l"(b));
}
__device__ __forceinline__ float2 upk2(unsigned long long v) {
    float2 f;
    asm("mov.b64 {%0, %1}, %2;" : "=f"(f.x), "=f"(f.y) : "l"(v));
    return f;
}

// ---------------- device scratch (static, allocation-free) ----------------
__device__ float d_P[(size_t)N_CNT * 4096];        // P[n][k][m]
__device__ float d_genv[(size_t)E_CNT * 128];      // gated equiv per edge
__device__ float d_envnodes[N_CNT * 128];          // normalized env per node
__device__ int   d_cnt[N_CNT];                     // zero at load & restored by k_scatter
__device__ int   d_off[N_CNT + 1];
__device__ int   d_cur[N_CNT];
__device__ int   d_eid[E_CNT];

// ---------------- CSR scan / scatter ----------------
__global__ void k_scan() {
    __shared__ int part[1024];
    int t = threadIdx.x;
    int base = t * 16;
    int loc[16];
    int s = 0;
#pragma unroll
    for (int i = 0; i < 16; i++) { loc[i] = s; s += d_cnt[base + i]; }
    part[t] = s;
    __syncthreads();
    for (int o = 1; o < 1024; o <<= 1) {
        int v = (t >= o) ? part[t - o] : 0;
        __syncthreads();
        part[t] += v;
        __syncthreads();
    }
    int excl = (t > 0) ? part[t - 1] : 0;
#pragma unroll
    for (int i = 0; i < 16; i++) {
        d_off[base + i] = excl + loc[i];
        d_cur[base + i] = excl + loc[i];
    }
    if (t == 1023) d_off[N_CNT] = part[1023];
}
__global__ void k_scatter(const int* __restrict__ ec) {
    int e = blockIdx.x * blockDim.x + threadIdx.x;
    if (e < E_CNT) {
        int n = ec[e];
        int pos = atomicAdd(&d_cur[n], 1);
        d_eid[pos] = e;
        if (e < N_CNT) d_cnt[e] = 0;   // restore invariant for next call
    }
}

// ---------------- mega-kernel: histogram + Q + P + GATE. 32 nodes / 512 edges per block ----
// dyn smem: sQ 16384 floats (64KB) | sB 8192 floats (32KB)
__global__ __launch_bounds__(256, 2) void k_QP(
    const float* __restrict__ ninv, const float* __restrict__ Wq,
    const float* __restrict__ Wk,   const int* __restrict__ ec,
    const float* __restrict__ scal, const float* __restrict__ equiv,
    const float* __restrict__ W_env, const float* __restrict__ b_env)
{
    extern __shared__ float sm[];
    float* sQ = sm;            // [32][512]
    float* sB = sQ + 16384;    // scratch
    int tid = threadIdx.x;
    int n0 = blockIdx.x * 32;

    { // fused histogram: 512 edges per block
        int e = blockIdx.x * 512 + tid;
        atomicAdd(&d_cnt[ec[e]], 1);
        atomicAdd(&d_cnt[ec[e + 256]], 1);
    }

    { // load ninv 32x64 coalesced
        const float4* src = (const float4*)(ninv + (size_t)n0 * 64);
        float4* dst = (float4*)sB;
        for (int i = tid; i < 512; i += 256) dst[i] = src[i];
    }
    __syncthreads();

    // --- Q ---
    float acc0[32], acc1[32];
#pragma unroll
    for (int j = 0; j < 32; j++) { acc0[j] = 0.f; acc1[j] = 0.f; }
    for (int k = 0; k < 64; k++) {
        float w0 = Wq[k * 512 + tid];
        float w1 = Wq[k * 512 + tid + 256];
#pragma unroll
        for (int j = 0; j < 32; j++) {
            float nv = sB[j * 64 + k];
            acc0[j] += nv * w0;
            acc1[j] += nv * w1;
        }
    }
#pragma unroll
    for (int j = 0; j < 32; j++) {
        sQ[j * 512 + tid]       = acc0[j];
        sQ[j * 512 + tid + 256] = acc1[j];
    }
    __syncthreads();

    // --- P ---
    {
        int m = tid & 31, ns = tid >> 5;
        float q[4][16];
#pragma unroll
        for (int j = 0; j < 4; j++) {
            const float4* Qp = (const float4*)(sQ + (ns * 4 + j) * 512 + m * 16);
#pragma unroll
            for (int v = 0; v < 4; v++) {
                float4 t = Qp[v];
                q[j][v * 4 + 0] = t.x; q[j][v * 4 + 1] = t.y;
                q[j][v * 4 + 2] = t.z; q[j][v * 4 + 3] = t.w;
            }
        }
        int f0 = m * 4;
        int cxor = (m >> 1) & 7;
        for (int kc = 0; kc < 128; kc += 16) {
            __syncthreads();
            {
                const float4* src = (const float4*)(Wk + (size_t)kc * 512);
                float4* dst = (float4*)sB;
                for (int i = tid; i < 2048; i += 256) {
                    int row = i >> 7, f = i & 127;
                    dst[row * 128 + SW4(f)] = src[i];
                }
            }
            __syncthreads();
#pragma unroll
            for (int kk = 0; kk < 16; kk++) {
                const float4* row4 = (const float4*)sB + kk * 128;
                float4 w0 = row4[(f0 + 0) ^ cxor];
                float4 w1 = row4[(f0 + 1) ^ cxor];
                float4 w2 = row4[(f0 + 2) ^ cxor];
                float4 w3 = row4[(f0 + 3) ^ cxor];
#pragma unroll
                for (int j = 0; j < 4; j++) {
                    float acc = q[j][0] * w0.x + q[j][1] * w0.y + q[j][2] * w0.z + q[j][3] * w0.w
                              + q[j][4] * w1.x + q[j][5] * w1.y + q[j][6] * w1.z + q[j][7] * w1.w
                              + q[j][8] * w2.x + q[j][9] * w2.y + q[j][10] * w2.z + q[j][11] * w2.w
                              + q[j][12] * w3.x + q[j][13] * w3.y + q[j][14] * w3.z + q[j][15] * w3.w;
                    int n = n0 + ns * 4 + j;
                    d_P[(size_t)n * 4096 + (kc + kk) * 32 + m] = acc;
                }
            }
        }
    }

    // --- GATE phase: genv = equiv * silu(scal @ W_env + b), 512 edges per block ---
    __syncthreads();
    { // W_env [128][64] into sB, once per block
        const float4* wsrc = (const float4*)W_env;
        float4* wdst = (float4*)sB;
        for (int i = tid; i < 2048; i += 256) wdst[i] = wsrc[i];
    }
    int col = tid & 63, grp = tid >> 6;   // 64 cols x 4 grps of 16 edges
    float bcol = b_env[col];
    float* sS = sQ;            // scal tile [64][128]
    float* sG = sQ + 8192;     // gates [64][65] padded

    for (int sub = 0; sub < 8; sub++) {
        long e0 = (long)blockIdx.x * 512 + sub * 64;
        __syncthreads();   // prior GEMM reads of sS done
        {
            const float4* ssrc = (const float4*)(scal + e0 * 128);
            float4* sdst = (float4*)sS;
            for (int i = tid; i < 2048; i += 256) sdst[i] = ssrc[i];
        }
        __syncthreads();

        float acc[16];
#pragma unroll
        for (int j = 0; j < 16; j++) acc[j] = 0.f;
        for (int k = 0; k < 128; k += 4) {
            float w0 = sB[(k + 0) * 64 + col];
            float w1 = sB[(k + 1) * 64 + col];
            float w2 = sB[(k + 2) * 64 + col];
            float w3 = sB[(k + 3) * 64 + col];
#pragma unroll
            for (int j = 0; j < 16; j++) {
                float4 s4 = *(const float4*)&sS[(grp * 16 + j) * 128 + k];  // broadcast
                acc[j] += s4.x * w0 + s4.y * w1 + s4.z * w2 + s4.w * w3;
            }
        }
#pragma unroll
        for (int j = 0; j < 16; j++) {
            float a = acc[j] + bcol;
            sG[(grp * 16 + j) * 65 + col] = a / (1.f + __expf(-a));
        }
        __syncthreads();

        // coalesced genv write: float4 per (edge, m)
        for (int i = tid; i < 2048; i += 256) {
            int el = i >> 5, mm = i & 31;
            float4 eq = ((const float4*)equiv)[(size_t)(e0 + el) * 32 + mm];
            float g0 = sG[el * 65 + 2 * mm];
            float g1 = sG[el * 65 + 2 * mm + 1];
            ((float4*)d_genv)[(size_t)(e0 + el) * 32 + mm] =
                make_float4(eq.x * g0, eq.y * g1, eq.z * g1, eq.w * g1);
        }
    }
}

// ---------------- per-node: logits(P) + softmax + genv aggregation + SO3 norm -----
// PERSISTENT, 128 threads, smem ~35 KB -> 6 blocks/SM.
__global__ __launch_bounds__(128, 6) void k_nodeA(const float* __restrict__ scal)
{
    extern __shared__ float sm[];
    float* P_s    = sm;                 // [k][m] 4096
    float* scal_s = P_s + 4096;         // [k][34]
    float* acc_s  = scal_s + 4352;      // [m][8]
    int*   eids   = (int*)(acc_s + 256);

    int tid = threadIdx.x;
    int mg = tid >> 3, es = tid & 7;
    int m0 = mg * 2;

    for (int n = blockIdx.x; n < N_CNT; n += gridDim.x) {
        __syncthreads();   // prior node fully done
        int beg = d_off[n];
        int cnt = d_off[n + 1] - beg;
        {
            const float4* Pg = (const float4*)(d_P + (size_t)n * 4096);
            float4* Pd = (float4*)P_s;
            for (int i = tid; i < 1024; i += 128) Pd[i] = Pg[i];
            for (int i = tid; i < 256; i += 128) acc_s[i] = 0.f;
        }

        for (int base = 0; base < cnt; base += 16) {
            __syncthreads();
            if (tid < 16) {
                int idx = base + tid;
                eids[tid] = (idx < cnt) ? d_eid[beg + idx] : -1;
            }
            __syncthreads();
            for (int i = tid; i < 512; i += 128) {
                int el = i >> 5, c = i & 31;
                int e = eids[el];
                float4 v = make_float4(0.f, 0.f, 0.f, 0.f);
                if (e >= 0) v = ((const float4*)scal)[(size_t)e * 32 + c];
                scal_s[(4 * c + 0) * 34 + el] = v.x;
                scal_s[(4 * c + 1) * 34 + el] = v.y;
                scal_s[(4 * c + 2) * 34 + el] = v.z;
                scal_s[(4 * c + 3) * 34 + el] = v.w;
            }
            __syncthreads();

            // logits only: 2 LDS + 2 FMA2 per k
            unsigned long long lg0 = 0ull, lg1 = 0ull;
#pragma unroll 8
            for (int k = 0; k < 128; k++) {
                float2 p  = *(const float2*)&P_s[k * 32 + m0];
                float2 ab = *(const float2*)&scal_s[k * 34 + 2 * es];
                unsigned long long p2 = pk2(p.x, p.y);
                fma2(lg0, p2, pk2(ab.x, ab.x));
                fma2(lg1, p2, pk2(ab.y, ab.y));
            }
            float2 l0 = upk2(lg0), l1 = upk2(lg1);

            float r0=0,r1=0,r2=0,r3=0,r4=0;
            float r5=0,r6=0,r7=0,r8=0,r9=0;
            int ei0 = es * 2, ei1 = ei0 + 1;
            int e0 = eids[ei0], e1 = eids[ei1];
            if (e0 >= 0) {
                float z0 = __expf(fminf(fmaxf(l0.x * 0.25f, -5.f), 5.f));
                float z1 = __expf(fminf(fmaxf(l0.y * 0.25f, -5.f), 5.f));
                float4 g0 = ((const float4*)d_genv)[(size_t)e0 * 32 + m0];
                float4 g1 = ((const float4*)d_genv)[(size_t)e0 * 32 + m0 + 1];
                r0 += z0; r1 += z0*g0.x; r2 += z0*g0.y; r3 += z0*g0.z; r4 += z0*g0.w;
                r5 += z1; r6 += z1*g1.x; r7 += z1*g1.y; r8 += z1*g1.z; r9 += z1*g1.w;
            }
            if (e1 >= 0) {
                float z0 = __expf(fminf(fmaxf(l1.x * 0.25f, -5.f), 5.f));
                float z1 = __expf(fminf(fmaxf(l1.y * 0.25f, -5.f), 5.f));
                float4 g0 = ((const float4*)d_genv)[(size_t)e1 * 32 + m0];
                float4 g1 = ((const float4*)d_genv)[(size_t)e1 * 32 + m0 + 1];
                r0 += z0; r1 += z0*g0.x; r2 += z0*g0.y; r3 += z0*g0.z; r4 += z0*g0.w;
                r5 += z1; r6 += z1*g1.x; r7 += z1*g1.y; r8 += z1*g1.z; r9 += z1*g1.w;
            }
#pragma unroll
            for (int o = 1; o <= 4; o <<= 1) {
                r0 += __shfl_xor_sync(0xffffffffu, r0, o);
                r1 += __shfl_xor_sync(0xffffffffu, r1, o);
                r2 += __shfl_xor_sync(0xffffffffu, r2, o);
                r3 += __shfl_xor_sync(0xffffffffu, r3, o);
                r4 += __shfl_xor_sync(0xffffffffu, r4, o);
                r5 += __shfl_xor_sync(0xffffffffu, r5, o);
                r6 += __shfl_xor_sync(0xffffffffu, r6, o);
                r7 += __shfl_xor_sync(0xffffffffu, r7, o);
                r8 += __shfl_xor_sync(0xffffffffu, r8, o);
                r9 += __shfl_xor_sync(0xffffffffu, r9, o);
            }
            if (es == 0) {
                acc_s[m0 * 8 + 0] += r0; acc_s[m0 * 8 + 1] += r1;
                acc_s[m0 * 8 + 2] += r2; acc_s[m0 * 8 + 3] += r3;
                acc_s[m0 * 8 + 4] += r4;
                acc_s[(m0 + 1) * 8 + 0] += r5; acc_s[(m0 + 1) * 8 + 1] += r6;
                acc_s[(m0 + 1) * 8 + 2] += r7; acc_s[(m0 + 1) * 8 + 3] += r8;
                acc_s[(m0 + 1) * 8 + 4] += r9;
            }
        }
        __syncthreads();

        if (tid < 32) {
            int m = tid;
            float den = acc_s[m * 8 + 0];
            float inv = den > 0.f ? 1.f / den : 0.f;
            float ax = acc_s[m * 8 + 1] * inv, ay = acc_s[m * 8 + 2] * inv;
            float az = acc_s[m * 8 + 3] * inv, aw = acc_s[m * 8 + 4] * inv;
            float s0 = ax * ax;
            float s1 = ay * ay + az * az + aw * aw;
#pragma unroll
            for (int o = 16; o; o >>= 1) {
                s0 += __shfl_xor_sync(0xffffffffu, s0, o);
                s1 += __shfl_xor_sync(0xffffffffu, s1, o);
            }
            float n0 = rsqrtf(s0 * (1.f / 32.f) + 1e-6f);
            float n1 = rsqrtf(s1 * (1.f / 96.f) + 1e-6f);
            *(float4*)&d_envnodes[(size_t)n * 128 + m * 4] =
                make_float4(ax * n0, ay * n1, az * n1, aw * n1);
        }
    }
}

// ---------------- edge phase B: PERSISTENT ----------------
__global__ __launch_bounds__(512, 1) void k_edgeB(
    const float* __restrict__ scal, const float* __restrict__ equiv,
    const float* __restrict__ cond, const float* __restrict__ ucoef,
    const float* __restrict__ W_mix, const float* __restrict__ b_mix,
    const float* __restrict__ W_sc,  const float* __restrict__ b_sc,
    const int* __restrict__ edge_center, const int* __restrict__ active,
    float* __restrict__ out)
{
    extern __shared__ float sm[];
    float* sWc = sm;                  // [80][256]
    float* sB  = sWc + 20480;         // [256]
    float* sF  = sB + 256;            // [64][80]
    float* sTp = sF + 5120;           // [64][32][8]

    int tid = threadIdx.x;

    for (int idx = tid; idx < 20480; idx += 512) {
        int i = idx >> 8, j = idx & 255;
        sWc[idx] = (j < 128) ? W_mix[i * 128 + j] : W_sc[i * 128 + (j - 128)];
    }
    if (tid < 256) sB[tid] = (tid < 128) ? b_mix[tid] : b_sc[tid - 128];

    float u = ucoef[0];
    float c_old = rsqrtf(u * u + 1.f);
    float c_new = u * c_old;

    int tCol = tid & 63, tRow = tid >> 6;
    int w = tid >> 5, m = tid & 31;

    for (int tile = blockIdx.x; tile < E_CNT / 64; tile += gridDim.x) {
        __syncthreads();
        long e0 = (long)tile * 64;

        for (int idx = tid; idx < 64 * 16; idx += 512) {
            int el = idx >> 4, i = idx & 15;
            sF[el * 80 + 64 + i] = cond[(e0 + el) * 16 + i];
        }

        {
            for (int rep = 0; rep < 4; rep++) {
                int el = w * 4 + rep;
                long e = e0 + el;
                int nidx = edge_center[e];
                float4 x = *(const float4*)(equiv + e * 128 + m * 4);
                float4 y = *(const float4*)(d_envnodes + (size_t)nidx * 128 + m * 4);
                float t0 = x.x * y.x;
                float t1 = x.x * y.y, t2 = x.x * y.z, t3 = x.x * y.w;
                float t4 = x.y * y.x, t5 = x.z * y.x, t6 = x.w * y.x;
                float t7 = (x.y * y.y + x.z * y.z + x.w * y.w) * 0.5773502691896258f;
                float s0 = t0 * t0;
                float s1 = t1 * t1 + t2 * t2 + t3 * t3;
                float s2 = t4 * t4 + t5 * t5 + t6 * t6;
                float s3 = t7 * t7;
#pragma unroll
                for (int o = 16; o; o >>= 1) {
                    s0 += __shfl_xor_sync(0xffffffffu, s0, o);
                    s1 += __shfl_xor_sync(0xffffffffu, s1, o);
                    s2 += __shfl_xor_sync(0xffffffffu, s2, o);
                    s3 += __shfl_xor_sync(0xffffffffu, s3, o);
                }
                float r0 = rsqrtf(s0 * (1.f / 32.f) + 1e-6f);
                float r1 = rsqrtf(s1 * (1.f / 96.f) + 1e-6f);
                float r2 = rsqrtf(s2 * (1.f / 96.f) + 1e-6f);
                float r3 = rsqrtf(s3 * (1.f / 32.f) + 1e-6f);
                t0 *= r0; t1 *= r1; t2 *= r1; t3 *= r1;
                t4 *= r2; t5 *= r2; t6 *= r2; t7 *= r3;
                float* tp = &sTp[(el * 32 + m) * 8];
                tp[0] = t0; tp[1] = t1; tp[2] = t2; tp[3] = t3;
                tp[4] = t4; tp[5] = t5; tp[6] = t6; tp[7] = t7;
                sF[el * 80 + m]      = t0;
                sF[el * 80 + 32 + m] = t7;
            }
        }
        __syncthreads();

        float4 bias4 = ((float4*)sB)[tCol];
        unsigned long long accA[8], accB[8];
#pragma unroll
        for (int i = 0; i < 8; i++) {
            accA[i] = pk2(bias4.x, bias4.y);
            accB[i] = pk2(bias4.z, bias4.w);
        }
        for (int kb = 0; kb < 80; kb += 4) {
            float4 fv[8];
#pragma unroll
            for (int i = 0; i < 8; i++)
                fv[i] = *(const float4*)&sF[(tRow * 8 + i) * 80 + kb];
#pragma unroll
            for (int kk = 0; kk < 4; kk++) {
                float4 w4 = ((const float4*)(sWc + (kb + kk) * 256))[tCol];
                unsigned long long wA = pk2(w4.x, w4.y);
                unsigned long long wB = pk2(w4.z, w4.w);
#pragma unroll
                for (int i = 0; i < 8; i++) {
                    float f = (kk == 0) ? fv[i].x : (kk == 1) ? fv[i].y
                            : (kk == 2) ? fv[i].z : fv[i].w;
                    unsigned long long ff = pk2(f, f);
                    fma2(accA[i], wA, ff);
                    fma2(accB[i], wB, ff);
                }
            }
        }

#pragma unroll
        for (int i = 0; i < 8; i++) {
            int el = tRow * 8 + i;
            long e = e0 + el;
            long r = active[e];
            float2 axy = upk2(accA[i]);
            float2 azw = upk2(accB[i]);
            float4 a = make_float4(axy.x, axy.y, azw.x, azw.y);
            if (tCol < 32) {
                int m2 = tCol;
                float* tp = &sTp[(el * 32 + m2) * 8];
                float4 ne;
                ne.x = a.x * tp[0] + a.y * tp[7];
                ne.y = a.z * tp[1] + a.w * tp[4];
                ne.z = a.z * tp[2] + a.w * tp[5];
                ne.w = a.z * tp[3] + a.w * tp[6];
                float4 b = *(const float4*)(equiv + r * 128 + m2 * 4);
                float4 o;
                o.x = c_old * b.x + c_new * ne.x;
                o.y = c_old * b.y + c_new * ne.y;
                o.z = c_old * b.z + c_new * ne.z;
                o.w = c_old * b.w + c_new * ne.w;
                *(float4*)(out + (long)E_CNT * 128 + r * 128 + m2 * 4) = o;
            } else {
                int jc = tCol - 32;
                float4 b = *(const float4*)(scal + r * 128 + jc * 4);
                float4 o;
                o.x = c_old * b.x + c_new * a.x;
                o.y = c_old * b.y + c_new * a.y;
                o.z = c_old * b.z + c_new * a.z;
                o.w = c_old * b.w + c_new * a.w;
                *(float4*)(out + r * 128 + jc * 4) = o;
            }
        }
    }
}

// ---------------- launch ----------------
extern "C" void kernel_launch(void* const* d_in, const int* in_sizes, int n_in,
                              void* d_out, int out_size)
{
    const float* scal  = (const float*)d_in[0];
    const float* equiv = (const float*)d_in[1];
    const float* ninv  = (const float*)d_in[2];
    const float* cond  = (const float*)d_in[3];
    const float* ucoef = (const float*)d_in[4];
    const float* W_env = (const float*)d_in[5];
    const float* b_env = (const float*)d_in[6];
    const float* Wq    = (const float*)d_in[7];
    const float* Wk    = (const float*)d_in[8];
    const float* W_mix = (const float*)d_in[9];
    const float* b_mix = (const float*)d_in[10];
    const float* W_sc  = (const float*)d_in[11];
    const float* b_sc  = (const float*)d_in[12];
    const int*   ec    = (const int*)d_in[13];
    const int*   act   = (const int*)d_in[14];
    float* out = (float*)d_out;

    const int SMEMQP = (16384 + 8192) * 4;
    cudaFuncSetAttribute(k_QP, cudaFuncAttributeMaxDynamicSharedMemorySize, SMEMQP);
    k_QP<<<N_CNT / 32, 256, SMEMQP>>>(ninv, Wq, Wk, ec,
                                      scal, equiv, W_env, b_env);   // 0 (hist+Q+P+gate)

    k_scan<<<1, 1024>>>();                                 // 1
    k_scatter<<<E_CNT / 256, 256>>>(ec);                   // 2

    const int SMEMA = (4096 + 4352 + 256 + 16) * 4;
    cudaFuncSetAttribute(k_nodeA, cudaFuncAttributeMaxDynamicSharedMemorySize, SMEMA);
    k_nodeA<<<148 * 6, 128, SMEMA>>>(scal);                // 3 <- profiled

    const int SMEMB = (20480 + 256 + 5120 + 16384) * 4;
    cudaFuncSetAttribute(k_edgeB, cudaFuncAttributeMaxDynamicSharedMemorySize, SMEMB);
    k_edgeB<<<148, 512, SMEMB>>>(scal, equiv, cond, ucoef,
                                 W_mix, b_mix, W_sc, b_sc, ec, act, out);  // 4
}

// round 13
// speedup vs baseline: 1.0018x; 1.0018x over previous
#include <cuda_runtime.h>
#include <math.h>

#define E_CNT 262144
#define N_CNT 16384

// XOR swizzle within a 128-float4 (512-float) row: kills 4-way LDS conflicts
#define SW4(f) ((f) ^ (((f) >> 3) & 7))

// ---------------- f32x2 packed-FMA helpers (bit-exact fp32) ----------------
__device__ __forceinline__ unsigned long long pk2(float lo, float hi) {
    unsigned long long r;
    asm("mov.b64 %0, {%1, %2};" : "=l"(r) : "f"(lo), "f"(hi));
    return r;
}
__device__ __forceinline__ void fma2(unsigned long long& d,
                                     unsigned long long a, unsigned long long b) {
    asm("fma.rn.f32x2 %0, %1, %2, %0;" : "+l"(d) : "l"(a), "l"(b));
}
__device__ __forceinline__ float2 upk2(unsigned long long v) {
    float2 f;
    asm("mov.b64 {%0, %1}, %2;" : "=f"(f.x), "=f"(f.y) : "l"(v));
    return f;
}

// ---------------- device scratch (static, allocation-free) ----------------
__device__ float d_P[(size_t)N_CNT * 4096];        // P[n][k][m]
__device__ float d_genv[(size_t)E_CNT * 128];      // gated equiv per edge
__device__ float d_envnodes[N_CNT * 128];          // normalized env per node
__device__ int   d_cnt[N_CNT];                     // zero at load & restored by k_scatter
__device__ int   d_off[N_CNT + 1];
__device__ int   d_cur[N_CNT];
__device__ int   d_eid[E_CNT];

// ---------------- CSR scan / scatter ----------------
__global__ void k_scan() {
    __shared__ int part[1024];
    int t = threadIdx.x;
    int base = t * 16;
    int loc[16];
    int s = 0;
#pragma unroll
    for (int i = 0; i < 16; i++) { loc[i] = s; s += d_cnt[base + i]; }
    part[t] = s;
    __syncthreads();
    for (int o = 1; o < 1024; o <<= 1) {
        int v = (t >= o) ? part[t - o] : 0;
        __syncthreads();
        part[t] += v;
        __syncthreads();
    }
    int excl = (t > 0) ? part[t - 1] : 0;
#pragma unroll
    for (int i = 0; i < 16; i++) {
        d_off[base + i] = excl + loc[i];
        d_cur[base + i] = excl + loc[i];
    }
    if (t == 1023) d_off[N_CNT] = part[1023];
}
__global__ void k_scatter(const int* __restrict__ ec) {
    int e = blockIdx.x * blockDim.x + threadIdx.x;
    if (e < E_CNT) {
        int n = ec[e];
        int pos = atomicAdd(&d_cur[n], 1);
        d_eid[pos] = e;
        if (e < N_CNT) d_cnt[e] = 0;   // restore invariant for next call
    }
}

// ---------------- mega-kernel: histogram + Q + P + GATE. 32 nodes / 512 edges per block ----
// dyn smem: sQ 16384 floats (64KB) | sB 8192 floats (32KB)
__global__ __launch_bounds__(256, 2) void k_QP(
    const float* __restrict__ ninv, const float* __restrict__ Wq,
    const float* __restrict__ Wk,   const int* __restrict__ ec,
    const float* __restrict__ scal, const float* __restrict__ equiv,
    const float* __restrict__ W_env, const float* __restrict__ b_env)
{
    extern __shared__ float sm[];
    float* sQ = sm;            // [32][512]
    float* sB = sQ + 16384;    // scratch
    int tid = threadIdx.x;
    int n0 = blockIdx.x * 32;

    { // fused histogram: 512 edges per block
        int e = blockIdx.x * 512 + tid;
        atomicAdd(&d_cnt[ec[e]], 1);
        atomicAdd(&d_cnt[ec[e + 256]], 1);
    }

    { // load ninv 32x64 coalesced
        const float4* src = (const float4*)(ninv + (size_t)n0 * 64);
        float4* dst = (float4*)sB;
        for (int i = tid; i < 512; i += 256) dst[i] = src[i];
    }
    __syncthreads();

    // --- Q ---
    float acc0[32], acc1[32];
#pragma unroll
    for (int j = 0; j < 32; j++) { acc0[j] = 0.f; acc1[j] = 0.f; }
    for (int k = 0; k < 64; k++) {
        float w0 = Wq[k * 512 + tid];
        float w1 = Wq[k * 512 + tid + 256];
#pragma unroll
        for (int j = 0; j < 32; j++) {
            float nv = sB[j * 64 + k];
            acc0[j] += nv * w0;
            acc1[j] += nv * w1;
        }
    }
#pragma unroll
    for (int j = 0; j < 32; j++) {
        sQ[j * 512 + tid]       = acc0[j];
        sQ[j * 512 + tid + 256] = acc1[j];
    }
    __syncthreads();

    // --- P ---
    {
        int m = tid & 31, ns = tid >> 5;
        float q[4][16];
#pragma unroll
        for (int j = 0; j < 4; j++) {
            const float4* Qp = (const float4*)(sQ + (ns * 4 + j) * 512 + m * 16);
#pragma unroll
            for (int v = 0; v < 4; v++) {
                float4 t = Qp[v];
                q[j][v * 4 + 0] = t.x; q[j][v * 4 + 1] = t.y;
                q[j][v * 4 + 2] = t.z; q[j][v * 4 + 3] = t.w;
            }
        }
        int f0 = m * 4;
        int cxor = (m >> 1) & 7;
        for (int kc = 0; kc < 128; kc += 16) {
            __syncthreads();
            {
                const float4* src = (const float4*)(Wk + (size_t)kc * 512);
                float4* dst = (float4*)sB;
                for (int i = tid; i < 2048; i += 256) {
                    int row = i >> 7, f = i & 127;
                    dst[row * 128 + SW4(f)] = src[i];
                }
            }
            __syncthreads();
#pragma unroll
            for (int kk = 0; kk < 16; kk++) {
                const float4* row4 = (const float4*)sB + kk * 128;
                float4 w0 = row4[(f0 + 0) ^ cxor];
                float4 w1 = row4[(f0 + 1) ^ cxor];
                float4 w2 = row4[(f0 + 2) ^ cxor];
                float4 w3 = row4[(f0 + 3) ^ cxor];
#pragma unroll
                for (int j = 0; j < 4; j++) {
                    float acc = q[j][0] * w0.x + q[j][1] * w0.y + q[j][2] * w0.z + q[j][3] * w0.w
                              + q[j][4] * w1.x + q[j][5] * w1.y + q[j][6] * w1.z + q[j][7] * w1.w
                              + q[j][8] * w2.x + q[j][9] * w2.y + q[j][10] * w2.z + q[j][11] * w2.w
                              + q[j][12] * w3.x + q[j][13] * w3.y + q[j][14] * w3.z + q[j][15] * w3.w;
                    int n = n0 + ns * 4 + j;
                    d_P[(size_t)n * 4096 + (kc + kk) * 32 + m] = acc;
                }
            }
        }
    }

    // --- GATE phase: genv = equiv * silu(scal @ W_env + b), 512 edges per block ---
    __syncthreads();
    { // W_env [128][64] into sB, once per block
        const float4* wsrc = (const float4*)W_env;
        float4* wdst = (float4*)sB;
        for (int i = tid; i < 2048; i += 256) wdst[i] = wsrc[i];
    }
    int col = tid & 63, grp = tid >> 6;   // 64 cols x 4 grps of 16 edges
    float bcol = b_env[col];
    float* sS = sQ;            // scal tile [64][128]
    float* sG = sQ + 8192;     // gates [64][65] padded

    for (int sub = 0; sub < 8; sub++) {
        long e0 = (long)blockIdx.x * 512 + sub * 64;
        __syncthreads();   // prior GEMM reads of sS done
        {
            const float4* ssrc = (const float4*)(scal + e0 * 128);
            float4* sdst = (float4*)sS;
            for (int i = tid; i < 2048; i += 256) sdst[i] = ssrc[i];
        }
        __syncthreads();

        float acc[16];
#pragma unroll
        for (int j = 0; j < 16; j++) acc[j] = 0.f;
        for (int k = 0; k < 128; k += 4) {
            float w0 = sB[(k + 0) * 64 + col];
            float w1 = sB[(k + 1) * 64 + col];
            float w2 = sB[(k + 2) * 64 + col];
            float w3 = sB[(k + 3) * 64 + col];
#pragma unroll
            for (int j = 0; j < 16; j++) {
                float4 s4 = *(const float4*)&sS[(grp * 16 + j) * 128 + k];  // broadcast
                acc[j] += s4.x * w0 + s4.y * w1 + s4.z * w2 + s4.w * w3;
            }
        }
#pragma unroll
        for (int j = 0; j < 16; j++) {
            float a = acc[j] + bcol;
            sG[(grp * 16 + j) * 65 + col] = a / (1.f + __expf(-a));
        }
        __syncthreads();

        // coalesced genv write: float4 per (edge, m)
        for (int i = tid; i < 2048; i += 256) {
            int el = i >> 5, mm = i & 31;
            float4 eq = ((const float4*)equiv)[(size_t)(e0 + el) * 32 + mm];
            float g0 = sG[el * 65 + 2 * mm];
            float g1 = sG[el * 65 + 2 * mm + 1];
            ((float4*)d_genv)[(size_t)(e0 + el) * 32 + mm] =
                make_float4(eq.x * g0, eq.y * g1, eq.z * g1, eq.w * g1);
        }
    }
}

// ---------------- per-node: logits(P) + softmax + genv aggregation + SO3 norm -----
// PERSISTENT, 128 threads, smem ~35 KB -> 6 blocks/SM.
__global__ __launch_bounds__(128, 6) void k_nodeA(const float* __restrict__ scal)
{
    extern __shared__ float sm[];
    float* P_s    = sm;                 // [k][m] 4096
    float* scal_s = P_s + 4096;         // [k][34]
    float* acc_s  = scal_s + 4352;      // [m][8]
    int*   eids   = (int*)(acc_s + 256);

    int tid = threadIdx.x;
    int mg = tid >> 3, es = tid & 7;
    int m0 = mg * 2;

    for (int n = blockIdx.x; n < N_CNT; n += gridDim.x) {
        __syncthreads();   // prior node fully done
        int beg = d_off[n];
        int cnt = d_off[n + 1] - beg;
        {
            const float4* Pg = (const float4*)(d_P + (size_t)n * 4096);
            float4* Pd = (float4*)P_s;
            for (int i = tid; i < 1024; i += 128) Pd[i] = Pg[i];
            for (int i = tid; i < 256; i += 128) acc_s[i] = 0.f;
        }

        for (int base = 0; base < cnt; base += 16) {
            __syncthreads();
            if (tid < 16) {
                int idx = base + tid;
                eids[tid] = (idx < cnt) ? d_eid[beg + idx] : -1;
            }
            __syncthreads();
            for (int i = tid; i < 512; i += 128) {
                int el = i >> 5, c = i & 31;
                int e = eids[el];
                float4 v = make_float4(0.f, 0.f, 0.f, 0.f);
                if (e >= 0) v = ((const float4*)scal)[(size_t)e * 32 + c];
                scal_s[(4 * c + 0) * 34 + el] = v.x;
                scal_s[(4 * c + 1) * 34 + el] = v.y;
                scal_s[(4 * c + 2) * 34 + el] = v.z;
                scal_s[(4 * c + 3) * 34 + el] = v.w;
            }
            __syncthreads();

            // logits only: 2 LDS + 2 FMA2 per k
            unsigned long long lg0 = 0ull, lg1 = 0ull;
#pragma unroll 8
            for (int k = 0; k < 128; k++) {
                float2 p  = *(const float2*)&P_s[k * 32 + m0];
                float2 ab = *(const float2*)&scal_s[k * 34 + 2 * es];
                unsigned long long p2 = pk2(p.x, p.y);
                fma2(lg0, p2, pk2(ab.x, ab.x));
                fma2(lg1, p2, pk2(ab.y, ab.y));
            }
            float2 l0 = upk2(lg0), l1 = upk2(lg1);

            float r0=0,r1=0,r2=0,r3=0,r4=0;
            float r5=0,r6=0,r7=0,r8=0,r9=0;
            int ei0 = es * 2, ei1 = ei0 + 1;
            int e0 = eids[ei0], e1 = eids[ei1];
            if (e0 >= 0) {
                float z0 = __expf(fminf(fmaxf(l0.x * 0.25f, -5.f), 5.f));
                float z1 = __expf(fminf(fmaxf(l0.y * 0.25f, -5.f), 5.f));
                float4 g0 = ((const float4*)d_genv)[(size_t)e0 * 32 + m0];
                float4 g1 = ((const float4*)d_genv)[(size_t)e0 * 32 + m0 + 1];
                r0 += z0; r1 += z0*g0.x; r2 += z0*g0.y; r3 += z0*g0.z; r4 += z0*g0.w;
                r5 += z1; r6 += z1*g1.x; r7 += z1*g1.y; r8 += z1*g1.z; r9 += z1*g1.w;
            }
            if (e1 >= 0) {
                float z0 = __expf(fminf(fmaxf(l1.x * 0.25f, -5.f), 5.f));
                float z1 = __expf(fminf(fmaxf(l1.y * 0.25f, -5.f), 5.f));
                float4 g0 = ((const float4*)d_genv)[(size_t)e1 * 32 + m0];
                float4 g1 = ((const float4*)d_genv)[(size_t)e1 * 32 + m0 + 1];
                r0 += z0; r1 += z0*g0.x; r2 += z0*g0.y; r3 += z0*g0.z; r4 += z0*g0.w;
                r5 += z1; r6 += z1*g1.x; r7 += z1*g1.y; r8 += z1*g1.z; r9 += z1*g1.w;
            }
#pragma unroll
            for (int o = 1; o <= 4; o <<= 1) {
                r0 += __shfl_xor_sync(0xffffffffu, r0, o);
                r1 += __shfl_xor_sync(0xffffffffu, r1, o);
                r2 += __shfl_xor_sync(0xffffffffu, r2, o);
                r3 += __shfl_xor_sync(0xffffffffu, r3, o);
                r4 += __shfl_xor_sync(0xffffffffu, r4, o);
                r5 += __shfl_xor_sync(0xffffffffu, r5, o);
                r6 += __shfl_xor_sync(0xffffffffu, r6, o);
                r7 += __shfl_xor_sync(0xffffffffu, r7, o);
                r8 += __shfl_xor_sync(0xffffffffu, r8, o);
                r9 += __shfl_xor_sync(0xffffffffu, r9, o);
            }
            if (es == 0) {
                acc_s[m0 * 8 + 0] += r0; acc_s[m0 * 8 + 1] += r1;
                acc_s[m0 * 8 + 2] += r2; acc_s[m0 * 8 + 3] += r3;
                acc_s[m0 * 8 + 4] += r4;
                acc_s[(m0 + 1) * 8 + 0] += r5; acc_s[(m0 + 1) * 8 + 1] += r6;
                acc_s[(m0 + 1) * 8 + 2] += r7; acc_s[(m0 + 1) * 8 + 3] += r8;
                acc_s[(m0 + 1) * 8 + 4] += r9;
            }
        }
        __syncthreads();

        if (tid < 32) {
            int m = tid;
            float den = acc_s[m * 8 + 0];
            float inv = den > 0.f ? 1.f / den : 0.f;
            float ax = acc_s[m * 8 + 1] * inv, ay = acc_s[m * 8 + 2] * inv;
            float az = acc_s[m * 8 + 3] * inv, aw = acc_s[m * 8 + 4] * inv;
            float s0 = ax * ax;
            float s1 = ay * ay + az * az + aw * aw;
#pragma unroll
            for (int o = 16; o; o >>= 1) {
                s0 += __shfl_xor_sync(0xffffffffu, s0, o);
                s1 += __shfl_xor_sync(0xffffffffu, s1, o);
            }
            float n0 = rsqrtf(s0 * (1.f / 32.f) + 1e-6f);
            float n1 = rsqrtf(s1 * (1.f / 96.f) + 1e-6f);
            *(float4*)&d_envnodes[(size_t)n * 128 + m * 4] =
                make_float4(ax * n0, ay * n1, az * n1, aw * n1);
        }
    }
}

// ---------------- edge phase B: PERSISTENT ----------------
__global__ __launch_bounds__(512, 1) void k_edgeB(
    const float* __restrict__ scal, const float* __restrict__ equiv,
    const float* __restrict__ cond, const float* __restrict__ ucoef,
    const float* __restrict__ W_mix, const float* __restrict__ b_mix,
    const float* __restrict__ W_sc,  const float* __restrict__ b_sc,
    const int* __restrict__ edge_center, const int* __restrict__ active,
    float* __restrict__ out)
{
    extern __shared__ float sm[];
    float* sWc = sm;                  // [80][256]
    float* sB  = sWc + 20480;         // [256]
    float* sF  = sB + 256;            // [64][80]
    float* sTp = sF + 5120;           // [64][32][8]

    int tid = threadIdx.x;

    for (int idx = tid; idx < 20480; idx += 512) {
        int i = idx >> 8, j = idx & 255;
        sWc[idx] = (j < 128) ? W_mix[i * 128 + j] : W_sc[i * 128 + (j - 128)];
    }
    if (tid < 256) sB[tid] = (tid < 128) ? b_mix[tid] : b_sc[tid - 128];

    float u = ucoef[0];
    float c_old = rsqrtf(u * u + 1.f);
    float c_new = u * c_old;

    int tCol = tid & 63, tRow = tid >> 6;
    int w = tid >> 5, m = tid & 31;

    for (int tile = blockIdx.x; tile < E_CNT / 64; tile += gridDim.x) {
        __syncthreads();
        long e0 = (long)tile * 64;

        for (int idx = tid; idx < 64 * 16; idx += 512) {
            int el = idx >> 4, i = idx & 15;
            sF[el * 80 + 64 + i] = cond[(e0 + el) * 16 + i];
        }

        {
            for (int rep = 0; rep < 4; rep++) {
                int el = w * 4 + rep;
                long e = e0 + el;
                int nidx = edge_center[e];
                float4 x = *(const float4*)(equiv + e * 128 + m * 4);
                float4 y = *(const float4*)(d_envnodes + (size_t)nidx * 128 + m * 4);
                float t0 = x.x * y.x;
                float t1 = x.x * y.y, t2 = x.x * y.z, t3 = x.x * y.w;
                float t4 = x.y * y.x, t5 = x.z * y.x, t6 = x.w * y.x;
                float t7 = (x.y * y.y + x.z * y.z + x.w * y.w) * 0.5773502691896258f;
                float s0 = t0 * t0;
                float s1 = t1 * t1 + t2 * t2 + t3 * t3;
                float s2 = t4 * t4 + t5 * t5 + t6 * t6;
                float s3 = t7 * t7;
#pragma unroll
                for (int o = 16; o; o >>= 1) {
                    s0 += __shfl_xor_sync(0xffffffffu, s0, o);
                    s1 += __shfl_xor_sync(0xffffffffu, s1, o);
                    s2 += __shfl_xor_sync(0xffffffffu, s2, o);
                    s3 += __shfl_xor_sync(0xffffffffu, s3, o);
                }
                float r0 = rsqrtf(s0 * (1.f / 32.f) + 1e-6f);
                float r1 = rsqrtf(s1 * (1.f / 96.f) + 1e-6f);
                float r2 = rsqrtf(s2 * (1.f / 96.f) + 1e-6f);
                float r3 = rsqrtf(s3 * (1.f / 32.f) + 1e-6f);
                t0 *= r0; t1 *= r1; t2 *= r1; t3 *= r1;
                t4 *= r2; t5 *= r2; t6 *= r2; t7 *= r3;
                float* tp = &sTp[(el * 32 + m) * 8];
                tp[0] = t0; tp[1] = t1; tp[2] = t2; tp[3] = t3;
                tp[4] = t4; tp[5] = t5; tp[6] = t6; tp[7] = t7;
                sF[el * 80 + m]      = t0;
                sF[el * 80 + 32 + m] = t7;
            }
        }
        __syncthreads();

        float4 bias4 = ((float4*)sB)[tCol];
        unsigned long long accA[8], accB[8];
#pragma unroll
        for (int i = 0; i < 8; i++) {
            accA[i] = pk2(bias4.x, bias4.y);
            accB[i] = pk2(bias4.z, bias4.w);
        }
        for (int kb = 0; kb < 80; kb += 4) {
            float4 fv[8];
#pragma unroll
            for (int i = 0; i < 8; i++)
                fv[i] = *(const float4*)&sF[(tRow * 8 + i) * 80 + kb];
#pragma unroll
            for (int kk = 0; kk < 4; kk++) {
                float4 w4 = ((const float4*)(sWc + (kb + kk) * 256))[tCol];
                unsigned long long wA = pk2(w4.x, w4.y);
                unsigned long long wB = pk2(w4.z, w4.w);
#pragma unroll
                for (int i = 0; i < 8; i++) {
                    float f = (kk == 0) ? fv[i].x : (kk == 1) ? fv[i].y
                            : (kk == 2) ? fv[i].z : fv[i].w;
                    unsigned long long ff = pk2(f, f);
                    fma2(accA[i], wA, ff);
                    fma2(accB[i], wB, ff);
                }
            }
        }

#pragma unroll
        for (int i = 0; i < 8; i++) {
            int el = tRow * 8 + i;
            long e = e0 + el;
            long r = active[e];
            float2 axy = upk2(accA[i]);
            float2 azw = upk2(accB[i]);
            float4 a = make_float4(axy.x, axy.y, azw.x, azw.y);
            if (tCol < 32) {
                int m2 = tCol;
                float* tp = &sTp[(el * 32 + m2) * 8];
                float4 ne;
                ne.x = a.x * tp[0] + a.y * tp[7];
                ne.y = a.z * tp[1] + a.w * tp[4];
                ne.z = a.z * tp[2] + a.w * tp[5];
                ne.w = a.z * tp[3] + a.w * tp[6];
                float4 b = *(const float4*)(equiv + r * 128 + m2 * 4);
                float4 o;
                o.x = c_old * b.x + c_new * ne.x;
                o.y = c_old * b.y + c_new * ne.y;
                o.z = c_old * b.z + c_new * ne.z;
                o.w = c_old * b.w + c_new * ne.w;
                *(float4*)(out + (long)E_CNT * 128 + r * 128 + m2 * 4) = o;
            } else {
                int jc = tCol - 32;
                float4 b = *(const float4*)(scal + r * 128 + jc * 4);
                float4 o;
                o.x = c_old * b.x + c_new * a.x;
                o.y = c_old * b.y + c_new * a.y;
                o.z = c_old * b.z + c_new * a.z;
                o.w = c_old * b.w + c_new * a.w;
                *(float4*)(out + r * 128 + jc * 4) = o;
            }
        }
    }
}

// ---------------- launch ----------------
extern "C" void kernel_launch(void* const* d_in, const int* in_sizes, int n_in,
                              void* d_out, int out_size)
{
    const float* scal  = (const float*)d_in[0];
    const float* equiv = (const float*)d_in[1];
    const float* ninv  = (const float*)d_in[2];
    const float* cond  = (const float*)d_in[3];
    const float* ucoef = (const float*)d_in[4];
    const float* W_env = (const float*)d_in[5];
    const float* b_env = (const float*)d_in[6];
    const float* Wq    = (const float*)d_in[7];
    const float* Wk    = (const float*)d_in[8];
    const float* W_mix = (const float*)d_in[9];
    const float* b_mix = (const float*)d_in[10];
    const float* W_sc  = (const float*)d_in[11];
    const float* b_sc  = (const float*)d_in[12];
    const int*   ec    = (const int*)d_in[13];
    const int*   act   = (const int*)d_in[14];
    float* out = (float*)d_out;

    const int SMEMQP = (16384 + 8192) * 4;
    cudaFuncSetAttribute(k_QP, cudaFuncAttributeMaxDynamicSharedMemorySize, SMEMQP);
    k_QP<<<N_CNT / 32, 256, SMEMQP>>>(ninv, Wq, Wk, ec,
                                      scal, equiv, W_env, b_env);   // 0 (hist+Q+P+gate)

    k_scan<<<1, 1024>>>();                                 // 1
    k_scatter<<<E_CNT / 256, 256>>>(ec);                   // 2

    const int SMEMA = (4096 + 4352 + 256 + 16) * 4;
    cudaFuncSetAttribute(k_nodeA, cudaFuncAttributeMaxDynamicSharedMemorySize, SMEMA);
    k_nodeA<<<148 * 6, 128, SMEMA>>>(scal);                // 3 <- profiled

    const int SMEMB = (20480 + 256 + 5120 + 16384) * 4;
    cudaFuncSetAttribute(k_edgeB, cudaFuncAttributeMaxDynamicSharedMemorySize, SMEMB);
    k_edgeB<<<148, 512, SMEMB>>>(scal, equiv, cond, ucoef,
                                 W_mix, b_mix, W_sc, b_sc, ec, act, out);  // 4
}